// round 2
// baseline (speedup 1.0000x reference)
#include <cuda_runtime.h>
#include <cuda_bf16.h>
#include <math.h>

// Problem constants
#define BB 2
#define SS 2048
#define HID 1024
#define NH 16
#define DK 64
#define MM (BB*SS)   // 4096 rows

// ---------------------------------------------------------------------------
// Scratch (device globals; no allocation allowed)
// ---------------------------------------------------------------------------
__device__ float g_q[BB*NH*SS*DK];   // [b,h,s,d]
__device__ float g_k[BB*NH*SS*DK];
__device__ float g_v[BB*NH*SS*DK];
__device__ float g_x[BB*SS*HID];     // attention output, [b,s,hid]

// ---------------------------------------------------------------------------
// GEMM: out = A[M,1024] @ W[1024,1024]^T + bias, optional per-row scale
// of A (1 + rowscale[row]) and optional transposed [b,h,s,d] output layout.
// Tiles: 128x128x8, 256 threads, 8x8 micro-tile split-half.
// ---------------------------------------------------------------------------
__global__ void __launch_bounds__(256)
gemm_kernel(const float* __restrict__ A,
            const float* __restrict__ W,
            const float* __restrict__ bias,
            const float* __restrict__ rowscale,   // may be null
            float* __restrict__ out,
            int transpose_out)
{
    __shared__ float As[8][132];
    __shared__ float Bs[8][132];

    const int tid  = threadIdx.x;
    const int trow = tid >> 4;     // 0..15
    const int tcol = tid & 15;     // 0..15
    const int bm0  = blockIdx.y * 128;
    const int bn0  = blockIdx.x * 128;

    const int lrow = tid >> 1;          // 0..127 (tile row for loads)
    const int k4   = (tid & 1) << 2;    // 0 or 4

    float ascale = 1.0f;
    if (rowscale) ascale = 1.0f + rowscale[bm0 + lrow];

    float acc[8][8];
    #pragma unroll
    for (int i = 0; i < 8; i++)
        #pragma unroll
        for (int j = 0; j < 8; j++) acc[i][j] = 0.0f;

    const float* Arow = A + (size_t)(bm0 + lrow) * 1024;
    const float* Wrow = W + (size_t)(bn0 + lrow) * 1024;

    for (int kt = 0; kt < 1024; kt += 8) {
        float4 av = *(const float4*)(Arow + kt + k4);
        av.x *= ascale; av.y *= ascale; av.z *= ascale; av.w *= ascale;
        As[k4 + 0][lrow] = av.x;
        As[k4 + 1][lrow] = av.y;
        As[k4 + 2][lrow] = av.z;
        As[k4 + 3][lrow] = av.w;

        float4 wv = *(const float4*)(Wrow + kt + k4);
        Bs[k4 + 0][lrow] = wv.x;
        Bs[k4 + 1][lrow] = wv.y;
        Bs[k4 + 2][lrow] = wv.z;
        Bs[k4 + 3][lrow] = wv.w;

        __syncthreads();

        #pragma unroll
        for (int kk = 0; kk < 8; kk++) {
            float ar[8], br[8];
            float4 t;
            t = *(const float4*)&As[kk][trow * 4];
            ar[0] = t.x; ar[1] = t.y; ar[2] = t.z; ar[3] = t.w;
            t = *(const float4*)&As[kk][64 + trow * 4];
            ar[4] = t.x; ar[5] = t.y; ar[6] = t.z; ar[7] = t.w;
            t = *(const float4*)&Bs[kk][tcol * 4];
            br[0] = t.x; br[1] = t.y; br[2] = t.z; br[3] = t.w;
            t = *(const float4*)&Bs[kk][64 + tcol * 4];
            br[4] = t.x; br[5] = t.y; br[6] = t.z; br[7] = t.w;
            #pragma unroll
            for (int i = 0; i < 8; i++)
                #pragma unroll
                for (int j = 0; j < 8; j++)
                    acc[i][j] += ar[i] * br[j];
        }
        __syncthreads();
    }

    // Epilogue
    #pragma unroll
    for (int ih = 0; ih < 2; ih++) {
        #pragma unroll
        for (int i = 0; i < 4; i++) {
            int row = bm0 + ih * 64 + trow * 4 + i;
            int bb  = row >> 11;          // /2048
            int ss  = row & 2047;
            #pragma unroll
            for (int jh = 0; jh < 2; jh++) {
                int col0 = bn0 + jh * 64 + tcol * 4;
                float4 v;
                v.x = acc[ih * 4 + i][jh * 4 + 0] + bias[col0 + 0];
                v.y = acc[ih * 4 + i][jh * 4 + 1] + bias[col0 + 1];
                v.z = acc[ih * 4 + i][jh * 4 + 2] + bias[col0 + 2];
                v.w = acc[ih * 4 + i][jh * 4 + 3] + bias[col0 + 3];
                if (transpose_out) {
                    int hh = col0 >> 6;
                    int dd = col0 & 63;
                    *(float4*)&out[(((size_t)bb * NH + hh) * SS + ss) * DK + dd] = v;
                } else {
                    *(float4*)&out[(size_t)row * HID + col0] = v;
                }
            }
        }
    }
}

// ---------------------------------------------------------------------------
// Flash attention: per (b,h), Br=128 query rows per block, Bc=64 key tiles.
// Q and K stored d-major in smem (transposed) so QK^T inner loop is
// LDS.128-light; V natural layout; P staged through smem for PV.
// ---------------------------------------------------------------------------
#define QST 136   // Qst row stride (row index = d, 128 cols + pad)
#define KST 68
#define VST 68
#define PST 68
#define ATT_SMEM ((64*QST + 64*KST + 64*VST + 128*PST) * 4)

__global__ void __launch_bounds__(256)
attn_kernel(const int* __restrict__ mask)
{
    extern __shared__ float sm[];
    float* Qst = sm;                    // [64 d][136]
    float* Kst = Qst + 64 * QST;        // [64 d][68]
    float* Vs  = Kst + 64 * KST;        // [64 c][68]
    float* Ps  = Vs  + 64 * VST;        // [128 r][68]

    const int tid = threadIdx.x;
    const int ty  = tid >> 4;   // 0..15 -> 8 query rows each
    const int tx  = tid & 15;   // 0..15 -> 4 cols each

    const int bh = blockIdx.y;          // 0..31
    const int b  = bh >> 4;
    const int h  = bh & 15;
    const int q0 = blockIdx.x * 128;

    const float* qptr = g_q + ((size_t)bh * SS + q0) * DK;
    const int* mrow = mask + b * SS;

    // Load Q tile transposed, pre-scaled by 1/sqrt(DK)=0.125
    for (int e = tid; e < 128 * 16; e += 256) {
        int r  = e >> 4;
        int d4 = (e & 15) << 2;
        float4 qv = *(const float4*)(qptr + (size_t)r * DK + d4);
        Qst[(d4 + 0) * QST + r] = qv.x * 0.125f;
        Qst[(d4 + 1) * QST + r] = qv.y * 0.125f;
        Qst[(d4 + 2) * QST + r] = qv.z * 0.125f;
        Qst[(d4 + 3) * QST + r] = qv.w * 0.125f;
    }

    float o_[8][4];
    float m_[8], l_[8];
    #pragma unroll
    for (int i = 0; i < 8; i++) {
        m_[i] = -1e30f;
        l_[i] = 0.0f;
        #pragma unroll
        for (int j = 0; j < 4; j++) o_[i][j] = 0.0f;
    }

    for (int kt = 0; kt < SS / 64; kt++) {
        __syncthreads();   // previous iteration's Ps/Vs consumers done

        // Load K (transposed) and V tiles
        const float* kptr = g_k + ((size_t)bh * SS + kt * 64) * DK;
        const float* vptr = g_v + ((size_t)bh * SS + kt * 64) * DK;
        for (int e = tid; e < 64 * 16; e += 256) {
            int c  = e >> 4;
            int d4 = (e & 15) << 2;
            float4 kv = *(const float4*)(kptr + (size_t)c * DK + d4);
            Kst[(d4 + 0) * KST + c] = kv.x;
            Kst[(d4 + 1) * KST + c] = kv.y;
            Kst[(d4 + 2) * KST + c] = kv.z;
            Kst[(d4 + 3) * KST + c] = kv.w;
            float4 vv = *(const float4*)(vptr + (size_t)c * DK + d4);
            *(float4*)&Vs[c * VST + d4] = vv;
        }
        __syncthreads();

        // Scores: s[i][j] = sum_d q[r][d]*k[c][d]
        float s_[8][4];
        #pragma unroll
        for (int i = 0; i < 8; i++)
            #pragma unroll
            for (int j = 0; j < 4; j++) s_[i][j] = 0.0f;

        #pragma unroll 8
        for (int d = 0; d < 64; d++) {
            float4 kf = *(const float4*)&Kst[d * KST + (tx << 2)];
            float4 qa = *(const float4*)&Qst[d * QST + (ty << 3)];
            float4 qb = *(const float4*)&Qst[d * QST + (ty << 3) + 4];
            float qr[8] = {qa.x, qa.y, qa.z, qa.w, qb.x, qb.y, qb.z, qb.w};
            float kr[4] = {kf.x, kf.y, kf.z, kf.w};
            #pragma unroll
            for (int i = 0; i < 8; i++)
                #pragma unroll
                for (int j = 0; j < 4; j++)
                    s_[i][j] += qr[i] * kr[j];
        }

        // Mask: where mask==0, score = -10000
        int4 m4 = *(const int4*)(mrow + kt * 64 + (tx << 2));
        float msel[4];
        msel[0] = (m4.x == 0) ? 0.0f : 1.0f;
        msel[1] = (m4.y == 0) ? 0.0f : 1.0f;
        msel[2] = (m4.z == 0) ? 0.0f : 1.0f;
        msel[3] = (m4.w == 0) ? 0.0f : 1.0f;
        #pragma unroll
        for (int i = 0; i < 8; i++) {
            #pragma unroll
            for (int j = 0; j < 4; j++) {
                s_[i][j] = (msel[j] == 0.0f) ? -10000.0f : s_[i][j];
            }
        }

        // Online softmax per row (reduce across tx group: 16 lanes)
        #pragma unroll
        for (int i = 0; i < 8; i++) {
            float mx = fmaxf(fmaxf(s_[i][0], s_[i][1]), fmaxf(s_[i][2], s_[i][3]));
            #pragma unroll
            for (int off = 8; off >= 1; off >>= 1)
                mx = fmaxf(mx, __shfl_xor_sync(0xffffffffu, mx, off, 16));
            float mnew  = fmaxf(m_[i], mx);
            float alpha = __expf(m_[i] - mnew);
            float rs = 0.0f;
            #pragma unroll
            for (int j = 0; j < 4; j++) {
                float p = __expf(s_[i][j] - mnew);
                s_[i][j] = p;
                rs += p;
            }
            #pragma unroll
            for (int off = 8; off >= 1; off >>= 1)
                rs += __shfl_xor_sync(0xffffffffu, rs, off, 16);
            l_[i] = l_[i] * alpha + rs;
            m_[i] = mnew;
            #pragma unroll
            for (int j = 0; j < 4; j++) o_[i][j] *= alpha;
        }

        // Stage P
        #pragma unroll
        for (int i = 0; i < 8; i++) {
            float4 pv = make_float4(s_[i][0], s_[i][1], s_[i][2], s_[i][3]);
            *(float4*)&Ps[(ty * 8 + i) * PST + (tx << 2)] = pv;
        }
        __syncthreads();

        // PV: o[i][j] += p[r][c] * V[c][oc]
        #pragma unroll 4
        for (int c = 0; c < 64; c++) {
            float4 vf = *(const float4*)&Vs[c * VST + (tx << 2)];
            #pragma unroll
            for (int i = 0; i < 8; i++) {
                float p = Ps[(ty * 8 + i) * PST + c];
                o_[i][0] += p * vf.x;
                o_[i][1] += p * vf.y;
                o_[i][2] += p * vf.z;
                o_[i][3] += p * vf.w;
            }
        }
    }

    // Epilogue: normalize and write [b,s,hid]
    #pragma unroll
    for (int i = 0; i < 8; i++) {
        int r = q0 + ty * 8 + i;
        float inv = 1.0f / l_[i];
        float4 v = make_float4(o_[i][0] * inv, o_[i][1] * inv,
                               o_[i][2] * inv, o_[i][3] * inv);
        *(float4*)&g_x[((size_t)b * SS + r) * HID + h * DK + (tx << 2)] = v;
    }
}

// ---------------------------------------------------------------------------
extern "C" void kernel_launch(void* const* d_in, const int* in_sizes, int n_in,
                              void* d_out, int out_size)
{
    const float* query = (const float*)d_in[0];
    const float* key   = (const float*)d_in[1];
    const float* value = (const float*)d_in[2];
    const float* bias  = (const float*)d_in[3];
    const int*   mask  = (const int*)d_in[4];
    const float* wq = (const float*)d_in[5];
    const float* bq = (const float*)d_in[6];
    const float* wk = (const float*)d_in[7];
    const float* bk = (const float*)d_in[8];
    const float* wv = (const float*)d_in[9];
    const float* bv = (const float*)d_in[10];
    const float* wo = (const float*)d_in[11];
    const float* bo = (const float*)d_in[12];
    float* out = (float*)d_out;

    float *qp, *kp, *vp, *xp;
    cudaGetSymbolAddress((void**)&qp, g_q);
    cudaGetSymbolAddress((void**)&kp, g_k);
    cudaGetSymbolAddress((void**)&vp, g_v);
    cudaGetSymbolAddress((void**)&xp, g_x);

    cudaFuncSetAttribute(attn_kernel,
                         cudaFuncAttributeMaxDynamicSharedMemorySize, ATT_SMEM);

    dim3 gg(HID / 128, MM / 128);   // (8, 32)
    gemm_kernel<<<gg, 256>>>(query, wq, bq, nullptr, qp, 1);
    gemm_kernel<<<gg, 256>>>(key,   wk, bk, bias,    kp, 1);
    gemm_kernel<<<gg, 256>>>(value, wv, bv, bias,    vp, 1);
    attn_kernel<<<dim3(SS / 128, BB * NH), 256, ATT_SMEM>>>(mask);
    gemm_kernel<<<gg, 256>>>(xp, wo, bo, nullptr, out, 0);
}

// round 3
// speedup vs baseline: 1.7604x; 1.7604x over previous
#include <cuda_runtime.h>
#include <cuda_bf16.h>
#include <math.h>

#define BB 2
#define SS 2048
#define HID 1024
#define NH 16
#define DK 64
#define MM (BB*SS)   // 4096

// ---------------------------------------------------------------------------
// Scratch
// ---------------------------------------------------------------------------
__device__ float g_q[BB*NH*SS*DK];   // [b,h,s,d]
__device__ float g_k[BB*NH*SS*DK];
__device__ float g_v[BB*NH*SS*DK];
__device__ float g_x[BB*SS*HID];     // attention output [b,s,hid]

// ---------------------------------------------------------------------------
// tf32 helpers
// ---------------------------------------------------------------------------
__device__ __forceinline__ unsigned f2tf(float x) {
    unsigned u;
    asm("cvt.rna.tf32.f32 %0, %1;" : "=r"(u) : "f"(x));
    return u;
}

__device__ __forceinline__ void mma_tf32(float& c0, float& c1, float& c2, float& c3,
                                         unsigned a0, unsigned a1, unsigned a2, unsigned a3,
                                         unsigned b0, unsigned b1) {
    asm volatile(
        "mma.sync.aligned.m16n8k8.row.col.f32.tf32.tf32.f32 "
        "{%0,%1,%2,%3},{%4,%5,%6,%7},{%8,%9},{%0,%1,%2,%3};"
        : "+f"(c0), "+f"(c1), "+f"(c2), "+f"(c3)
        : "r"(a0), "r"(a1), "r"(a2), "r"(a3), "r"(b0), "r"(b1));
}

// ---------------------------------------------------------------------------
// GEMM: out = A[M,1024] @ W[1024,1024]^T + bias  (tf32 tensor cores)
// optional A row scale (1+rowscale[row]); optional [b,h,s,d] output layout.
// Tiles: BM=128, BN=128, BK=16; 8 warps, warp tile 64x32 (4 m-frag x 4 n-frag).
// ---------------------------------------------------------------------------
__global__ void __launch_bounds__(256)
gemm_tf32(const float* __restrict__ A,
          const float* __restrict__ W,
          const float* __restrict__ bias,
          const float* __restrict__ rowscale,
          float* __restrict__ out,
          int transpose_out)
{
    __shared__ unsigned At[16][132];   // [k][m]
    __shared__ unsigned Bt[16][132];   // [k][n]

    const int tid   = threadIdx.x;
    const int warp  = tid >> 5;
    const int lane  = tid & 31;
    const int g     = lane >> 2;   // 0..7
    const int q     = lane & 3;    // 0..3
    const int warpM = warp >> 2;   // 0..1
    const int warpN = warp & 3;    // 0..3
    const int bm0   = blockIdx.y * 128;
    const int bn0   = blockIdx.x * 128;

    const int lr = tid >> 1;           // 0..127
    const int lk = (tid & 1) << 3;     // 0 or 8

    float ascale = 1.0f;
    if (rowscale) ascale = 1.0f + rowscale[bm0 + lr];

    const float* Ap = A + (size_t)(bm0 + lr) * 1024 + lk;
    const float* Wp = W + (size_t)(bn0 + lr) * 1024 + lk;

    float acc[4][4][4];
    #pragma unroll
    for (int mt = 0; mt < 4; mt++)
        #pragma unroll
        for (int nt = 0; nt < 4; nt++)
            #pragma unroll
            for (int i = 0; i < 4; i++) acc[mt][nt][i] = 0.0f;

    for (int kt = 0; kt < 1024; kt += 16) {
        float4 av0 = *(const float4*)(Ap + kt);
        float4 av1 = *(const float4*)(Ap + kt + 4);
        float4 wv0 = *(const float4*)(Wp + kt);
        float4 wv1 = *(const float4*)(Wp + kt + 4);

        __syncthreads();
        At[lk + 0][lr] = f2tf(av0.x * ascale);
        At[lk + 1][lr] = f2tf(av0.y * ascale);
        At[lk + 2][lr] = f2tf(av0.z * ascale);
        At[lk + 3][lr] = f2tf(av0.w * ascale);
        At[lk + 4][lr] = f2tf(av1.x * ascale);
        At[lk + 5][lr] = f2tf(av1.y * ascale);
        At[lk + 6][lr] = f2tf(av1.z * ascale);
        At[lk + 7][lr] = f2tf(av1.w * ascale);
        Bt[lk + 0][lr] = f2tf(wv0.x);
        Bt[lk + 1][lr] = f2tf(wv0.y);
        Bt[lk + 2][lr] = f2tf(wv0.z);
        Bt[lk + 3][lr] = f2tf(wv0.w);
        Bt[lk + 4][lr] = f2tf(wv1.x);
        Bt[lk + 5][lr] = f2tf(wv1.y);
        Bt[lk + 6][lr] = f2tf(wv1.z);
        Bt[lk + 7][lr] = f2tf(wv1.w);
        __syncthreads();

        #pragma unroll
        for (int kk = 0; kk < 16; kk += 8) {
            unsigned af[4][4];
            #pragma unroll
            for (int mt = 0; mt < 4; mt++) {
                int r = warpM * 64 + mt * 16 + g;
                af[mt][0] = At[kk + q][r];
                af[mt][1] = At[kk + q][r + 8];
                af[mt][2] = At[kk + 4 + q][r];
                af[mt][3] = At[kk + 4 + q][r + 8];
            }
            unsigned bf[4][2];
            #pragma unroll
            for (int nt = 0; nt < 4; nt++) {
                int n = warpN * 32 + nt * 8 + g;
                bf[nt][0] = Bt[kk + q][n];
                bf[nt][1] = Bt[kk + 4 + q][n];
            }
            #pragma unroll
            for (int mt = 0; mt < 4; mt++)
                #pragma unroll
                for (int nt = 0; nt < 4; nt++)
                    mma_tf32(acc[mt][nt][0], acc[mt][nt][1], acc[mt][nt][2], acc[mt][nt][3],
                             af[mt][0], af[mt][1], af[mt][2], af[mt][3],
                             bf[nt][0], bf[nt][1]);
        }
    }

    // Epilogue: C layout — rows g (+8), cols 2q (+1)
    #pragma unroll
    for (int mt = 0; mt < 4; mt++) {
        #pragma unroll
        for (int nt = 0; nt < 4; nt++) {
            int col = bn0 + warpN * 32 + nt * 8 + 2 * q;
            float b0 = bias[col], b1 = bias[col + 1];
            #pragma unroll
            for (int half = 0; half < 2; half++) {
                int row = bm0 + warpM * 64 + mt * 16 + g + half * 8;
                float2 v;
                v.x = acc[mt][nt][half * 2 + 0] + b0;
                v.y = acc[mt][nt][half * 2 + 1] + b1;
                if (transpose_out) {
                    int bb = row >> 11, ss = row & 2047;
                    int hh = col >> 6, dd = col & 63;
                    *(float2*)&out[(((size_t)bb * NH + hh) * SS + ss) * DK + dd] = v;
                } else {
                    *(float2*)&out[(size_t)row * HID + col] = v;
                }
            }
        }
    }
}

// ---------------------------------------------------------------------------
// Flash attention with tf32 mma.
// Per (b,h): Br=128 query rows/block, Bc=64 key cols/tile, DK=64.
// 8 warps; warp w owns query rows w*16..w*16+15 and all 64 cols -> softmax
// reductions are intra-warp (4-lane quad shuffles).
// ---------------------------------------------------------------------------
#define QTS 132
#define KTS 68
#define VTS 68
#define PTS 68
#define ATT_SMEM ((64*QTS + 64*KTS + 64*VTS + 128*PTS + 64) * 4)

__global__ void __launch_bounds__(256)
attn_tf32(const int* __restrict__ mask)
{
    extern __shared__ unsigned sm[];
    unsigned* Qt = sm;                    // [64 d][132]  A-layout (k-major)
    unsigned* Kt = Qt + 64 * QTS;         // [64 d][68]   B-layout for QK^T
    unsigned* Vt = Kt + 64 * KTS;         // [64 c][68]   B-layout for PV
    unsigned* Ps = Vt + 64 * VTS;         // [128 r][68]  A-layout for PV
    float* maskF = (float*)(Ps + 128 * PTS);   // [64]

    const int tid  = threadIdx.x;
    const int warp = tid >> 5;
    const int lane = tid & 31;
    const int g    = lane >> 2;    // 0..7
    const int q    = lane & 3;     // 0..3

    const int bh = blockIdx.y;
    const int b  = bh >> 4;
    const int h  = bh & 15;
    const int q0 = blockIdx.x * 128;

    const int rloc = warp * 16 + g;        // local row (also +8)

    // Load Q (pre-scaled by 1/sqrt(64)=0.125), transposed to [d][r]
    const float* qptr = g_q + ((size_t)bh * SS + q0) * DK;
    for (int e = tid; e < 128 * 16; e += 256) {
        int r  = e >> 4;
        int d4 = (e & 15) << 2;
        float4 v = *(const float4*)(qptr + (size_t)r * DK + d4);
        Qt[(d4 + 0) * QTS + r] = f2tf(v.x * 0.125f);
        Qt[(d4 + 1) * QTS + r] = f2tf(v.y * 0.125f);
        Qt[(d4 + 2) * QTS + r] = f2tf(v.z * 0.125f);
        Qt[(d4 + 3) * QTS + r] = f2tf(v.w * 0.125f);
    }

    float o[8][4];
    #pragma unroll
    for (int nt = 0; nt < 8; nt++)
        #pragma unroll
        for (int i = 0; i < 4; i++) o[nt][i] = 0.0f;
    float mrow[2] = {-1e30f, -1e30f};
    float lrow[2] = {0.0f, 0.0f};

    for (int kt = 0; kt < SS / 64; kt++) {
        __syncthreads();   // previous PV done with Kt/Vt/Ps

        const float* kp = g_k + ((size_t)bh * SS + kt * 64) * DK;
        const float* vp = g_v + ((size_t)bh * SS + kt * 64) * DK;
        for (int e = tid; e < 64 * 16; e += 256) {
            int c  = e >> 4;
            int d4 = (e & 15) << 2;
            float4 kv = *(const float4*)(kp + (size_t)c * DK + d4);
            Kt[(d4 + 0) * KTS + c] = f2tf(kv.x);
            Kt[(d4 + 1) * KTS + c] = f2tf(kv.y);
            Kt[(d4 + 2) * KTS + c] = f2tf(kv.z);
            Kt[(d4 + 3) * KTS + c] = f2tf(kv.w);
            float4 vv = *(const float4*)(vp + (size_t)c * DK + d4);
            Vt[c * VTS + d4 + 0] = f2tf(vv.x);
            Vt[c * VTS + d4 + 1] = f2tf(vv.y);
            Vt[c * VTS + d4 + 2] = f2tf(vv.z);
            Vt[c * VTS + d4 + 3] = f2tf(vv.w);
        }
        if (tid < 64)
            maskF[tid] = (mask[b * SS + kt * 64 + tid] == 0) ? 0.0f : 1.0f;
        __syncthreads();

        // ---- S = Q K^T ----
        float s[8][4];
        #pragma unroll
        for (int nt = 0; nt < 8; nt++)
            #pragma unroll
            for (int i = 0; i < 4; i++) s[nt][i] = 0.0f;

        #pragma unroll
        for (int k8 = 0; k8 < 64; k8 += 8) {
            unsigned a0 = Qt[(k8 + q) * QTS + q0 * 0 + rloc];
            unsigned a1 = Qt[(k8 + q) * QTS + rloc + 8];
            unsigned a2 = Qt[(k8 + 4 + q) * QTS + rloc];
            unsigned a3 = Qt[(k8 + 4 + q) * QTS + rloc + 8];
            #pragma unroll
            for (int nt = 0; nt < 8; nt++) {
                unsigned b0 = Kt[(k8 + q) * KTS + nt * 8 + g];
                unsigned b1 = Kt[(k8 + 4 + q) * KTS + nt * 8 + g];
                mma_tf32(s[nt][0], s[nt][1], s[nt][2], s[nt][3],
                         a0, a1, a2, a3, b0, b1);
            }
        }

        // ---- mask ----
        #pragma unroll
        for (int nt = 0; nt < 8; nt++) {
            float mk0 = maskF[nt * 8 + 2 * q];
            float mk1 = maskF[nt * 8 + 2 * q + 1];
            s[nt][0] = (mk0 == 0.0f) ? -10000.0f : s[nt][0];
            s[nt][2] = (mk0 == 0.0f) ? -10000.0f : s[nt][2];
            s[nt][1] = (mk1 == 0.0f) ? -10000.0f : s[nt][1];
            s[nt][3] = (mk1 == 0.0f) ? -10000.0f : s[nt][3];
        }

        // ---- online softmax (two rows per thread) ----
        #pragma unroll
        for (int half = 0; half < 2; half++) {
            float mx = -1e30f;
            #pragma unroll
            for (int nt = 0; nt < 8; nt++) {
                mx = fmaxf(mx, s[nt][half * 2 + 0]);
                mx = fmaxf(mx, s[nt][half * 2 + 1]);
            }
            mx = fmaxf(mx, __shfl_xor_sync(0xffffffffu, mx, 1));
            mx = fmaxf(mx, __shfl_xor_sync(0xffffffffu, mx, 2));
            float mnew  = fmaxf(mrow[half], mx);
            float alpha = __expf(mrow[half] - mnew);
            float rs = 0.0f;
            #pragma unroll
            for (int nt = 0; nt < 8; nt++) {
                float p0 = __expf(s[nt][half * 2 + 0] - mnew);
                float p1 = __expf(s[nt][half * 2 + 1] - mnew);
                s[nt][half * 2 + 0] = p0;
                s[nt][half * 2 + 1] = p1;
                rs += p0 + p1;
            }
            rs += __shfl_xor_sync(0xffffffffu, rs, 1);
            rs += __shfl_xor_sync(0xffffffffu, rs, 2);
            lrow[half] = lrow[half] * alpha + rs;
            mrow[half] = mnew;
            #pragma unroll
            for (int nt = 0; nt < 8; nt++) {
                o[nt][half * 2 + 0] *= alpha;
                o[nt][half * 2 + 1] *= alpha;
            }
        }

        // ---- stage P (A-layout [r][c], stride 68 -> conflict-free frag loads)
        #pragma unroll
        for (int nt = 0; nt < 8; nt++) {
            Ps[rloc * PTS + nt * 8 + 2 * q]           = f2tf(s[nt][0]);
            Ps[rloc * PTS + nt * 8 + 2 * q + 1]       = f2tf(s[nt][1]);
            Ps[(rloc + 8) * PTS + nt * 8 + 2 * q]     = f2tf(s[nt][2]);
            Ps[(rloc + 8) * PTS + nt * 8 + 2 * q + 1] = f2tf(s[nt][3]);
        }
        __syncthreads();

        // ---- O += P V ----
        #pragma unroll
        for (int c8 = 0; c8 < 64; c8 += 8) {
            unsigned a0 = Ps[rloc * PTS + c8 + q];
            unsigned a1 = Ps[(rloc + 8) * PTS + c8 + q];
            unsigned a2 = Ps[rloc * PTS + c8 + 4 + q];
            unsigned a3 = Ps[(rloc + 8) * PTS + c8 + 4 + q];
            #pragma unroll
            for (int nt = 0; nt < 8; nt++) {
                unsigned b0 = Vt[(c8 + q) * VTS + nt * 8 + g];
                unsigned b1 = Vt[(c8 + 4 + q) * VTS + nt * 8 + g];
                mma_tf32(o[nt][0], o[nt][1], o[nt][2], o[nt][3],
                         a0, a1, a2, a3, b0, b1);
            }
        }
    }

    // Epilogue: normalize and write [b,s,hid]
    float inv0 = 1.0f / lrow[0];
    float inv1 = 1.0f / lrow[1];
    #pragma unroll
    for (int nt = 0; nt < 8; nt++) {
        int d = nt * 8 + 2 * q;
        int rowA = q0 + rloc;
        int rowB = rowA + 8;
        float2 v0 = make_float2(o[nt][0] * inv0, o[nt][1] * inv0);
        float2 v1 = make_float2(o[nt][2] * inv1, o[nt][3] * inv1);
        *(float2*)&g_x[((size_t)b * SS + rowA) * HID + h * DK + d] = v0;
        *(float2*)&g_x[((size_t)b * SS + rowB) * HID + h * DK + d] = v1;
    }
}

// ---------------------------------------------------------------------------
extern "C" void kernel_launch(void* const* d_in, const int* in_sizes, int n_in,
                              void* d_out, int out_size)
{
    const float* query = (const float*)d_in[0];
    const float* key   = (const float*)d_in[1];
    const float* value = (const float*)d_in[2];
    const float* bias  = (const float*)d_in[3];
    const int*   mask  = (const int*)d_in[4];
    const float* wq = (const float*)d_in[5];
    const float* bq = (const float*)d_in[6];
    const float* wk = (const float*)d_in[7];
    const float* bk = (const float*)d_in[8];
    const float* wv = (const float*)d_in[9];
    const float* bv = (const float*)d_in[10];
    const float* wo = (const float*)d_in[11];
    const float* bo = (const float*)d_in[12];
    float* out = (float*)d_out;

    float *qp, *kp, *vp, *xp;
    cudaGetSymbolAddress((void**)&qp, g_q);
    cudaGetSymbolAddress((void**)&kp, g_k);
    cudaGetSymbolAddress((void**)&vp, g_v);
    cudaGetSymbolAddress((void**)&xp, g_x);

    cudaFuncSetAttribute(attn_tf32,
                         cudaFuncAttributeMaxDynamicSharedMemorySize, ATT_SMEM);

    dim3 gg(HID / 128, MM / 128);   // (8, 32)
    gemm_tf32<<<gg, 256>>>(query, wq, bq, nullptr, qp, 1);
    gemm_tf32<<<gg, 256>>>(key,   wk, bk, bias,    kp, 1);
    gemm_tf32<<<gg, 256>>>(value, wv, bv, bias,    vp, 1);
    attn_tf32<<<dim3(SS / 128, BB * NH), 256, ATT_SMEM>>>(mask);
    gemm_tf32<<<gg, 256>>>(xp, wo, bo, nullptr, out, 0);
}

// round 4
// speedup vs baseline: 2.3124x; 1.3136x over previous
#include <cuda_runtime.h>
#include <cuda_bf16.h>
#include <math.h>

#define BB 2
#define SS 2048
#define HID 1024
#define NH 16
#define DK 64
#define MM (BB*SS)   // 4096

// ---------------------------------------------------------------------------
// Scratch
// ---------------------------------------------------------------------------
__device__ float g_q[BB*NH*SS*DK];   // [b,h,s,d]
__device__ float g_k[BB*NH*SS*DK];
__device__ float g_v[BB*NH*SS*DK];
__device__ float g_x[BB*SS*HID];     // attention output [b,s,hid]

// ---------------------------------------------------------------------------
// tf32 helpers
// ---------------------------------------------------------------------------
__device__ __forceinline__ unsigned f2tf(float x) {
    unsigned u;
    asm("cvt.rna.tf32.f32 %0, %1;" : "=r"(u) : "f"(x));
    return u;
}

__device__ __forceinline__ void mma_tf32(float& c0, float& c1, float& c2, float& c3,
                                         unsigned a0, unsigned a1, unsigned a2, unsigned a3,
                                         unsigned b0, unsigned b1) {
    asm volatile(
        "mma.sync.aligned.m16n8k8.row.col.f32.tf32.tf32.f32 "
        "{%0,%1,%2,%3},{%4,%5,%6,%7},{%8,%9},{%0,%1,%2,%3};"
        : "+f"(c0), "+f"(c1), "+f"(c2), "+f"(c3)
        : "r"(a0), "r"(a1), "r"(a2), "r"(a3), "r"(b0), "r"(b1));
}

// ---------------------------------------------------------------------------
// GEMM: out = A[M,1024] @ W[1024,1024]^T + bias  (tf32 tensor cores)
// ---------------------------------------------------------------------------
__global__ void __launch_bounds__(256)
gemm_tf32(const float* __restrict__ A,
          const float* __restrict__ W,
          const float* __restrict__ bias,
          const float* __restrict__ rowscale,
          float* __restrict__ out,
          int transpose_out)
{
    __shared__ unsigned At[16][132];   // [k][m]
    __shared__ unsigned Bt[16][132];   // [k][n]

    const int tid   = threadIdx.x;
    const int warp  = tid >> 5;
    const int lane  = tid & 31;
    const int g     = lane >> 2;
    const int q     = lane & 3;
    const int warpM = warp >> 2;
    const int warpN = warp & 3;
    const int bm0   = blockIdx.y * 128;
    const int bn0   = blockIdx.x * 128;

    const int lr = tid >> 1;
    const int lk = (tid & 1) << 3;

    float ascale = 1.0f;
    if (rowscale) ascale = 1.0f + rowscale[bm0 + lr];

    const float* Ap = A + (size_t)(bm0 + lr) * 1024 + lk;
    const float* Wp = W + (size_t)(bn0 + lr) * 1024 + lk;

    float acc[4][4][4];
    #pragma unroll
    for (int mt = 0; mt < 4; mt++)
        #pragma unroll
        for (int nt = 0; nt < 4; nt++)
            #pragma unroll
            for (int i = 0; i < 4; i++) acc[mt][nt][i] = 0.0f;

    for (int kt = 0; kt < 1024; kt += 16) {
        float4 av0 = *(const float4*)(Ap + kt);
        float4 av1 = *(const float4*)(Ap + kt + 4);
        float4 wv0 = *(const float4*)(Wp + kt);
        float4 wv1 = *(const float4*)(Wp + kt + 4);

        __syncthreads();
        At[lk + 0][lr] = f2tf(av0.x * ascale);
        At[lk + 1][lr] = f2tf(av0.y * ascale);
        At[lk + 2][lr] = f2tf(av0.z * ascale);
        At[lk + 3][lr] = f2tf(av0.w * ascale);
        At[lk + 4][lr] = f2tf(av1.x * ascale);
        At[lk + 5][lr] = f2tf(av1.y * ascale);
        At[lk + 6][lr] = f2tf(av1.z * ascale);
        At[lk + 7][lr] = f2tf(av1.w * ascale);
        Bt[lk + 0][lr] = f2tf(wv0.x);
        Bt[lk + 1][lr] = f2tf(wv0.y);
        Bt[lk + 2][lr] = f2tf(wv0.z);
        Bt[lk + 3][lr] = f2tf(wv0.w);
        Bt[lk + 4][lr] = f2tf(wv1.x);
        Bt[lk + 5][lr] = f2tf(wv1.y);
        Bt[lk + 6][lr] = f2tf(wv1.z);
        Bt[lk + 7][lr] = f2tf(wv1.w);
        __syncthreads();

        #pragma unroll
        for (int kk = 0; kk < 16; kk += 8) {
            unsigned af[4][4];
            #pragma unroll
            for (int mt = 0; mt < 4; mt++) {
                int r = warpM * 64 + mt * 16 + g;
                af[mt][0] = At[kk + q][r];
                af[mt][1] = At[kk + q][r + 8];
                af[mt][2] = At[kk + 4 + q][r];
                af[mt][3] = At[kk + 4 + q][r + 8];
            }
            unsigned bf[4][2];
            #pragma unroll
            for (int nt = 0; nt < 4; nt++) {
                int n = warpN * 32 + nt * 8 + g;
                bf[nt][0] = Bt[kk + q][n];
                bf[nt][1] = Bt[kk + 4 + q][n];
            }
            #pragma unroll
            for (int mt = 0; mt < 4; mt++)
                #pragma unroll
                for (int nt = 0; nt < 4; nt++)
                    mma_tf32(acc[mt][nt][0], acc[mt][nt][1], acc[mt][nt][2], acc[mt][nt][3],
                             af[mt][0], af[mt][1], af[mt][2], af[mt][3],
                             bf[nt][0], bf[nt][1]);
        }
    }

    #pragma unroll
    for (int mt = 0; mt < 4; mt++) {
        #pragma unroll
        for (int nt = 0; nt < 4; nt++) {
            int col = bn0 + warpN * 32 + nt * 8 + 2 * q;
            float b0 = bias[col], b1 = bias[col + 1];
            #pragma unroll
            for (int half = 0; half < 2; half++) {
                int row = bm0 + warpM * 64 + mt * 16 + g + half * 8;
                float2 v;
                v.x = acc[mt][nt][half * 2 + 0] + b0;
                v.y = acc[mt][nt][half * 2 + 1] + b1;
                if (transpose_out) {
                    int bb = row >> 11, ss = row & 2047;
                    int hh = col >> 6, dd = col & 63;
                    *(float2*)&out[(((size_t)bb * NH + hh) * SS + ss) * DK + dd] = v;
                } else {
                    *(float2*)&out[(size_t)row * HID + col] = v;
                }
            }
        }
    }
}

// ---------------------------------------------------------------------------
// Flash attention, tf32 mma, 4 warps, warp tile m32 x n64.
// Br=128 rows/CTA, Bc=64 cols/tile.
//   Qt[d=64][136]  (k-major A layout; frag load bank = 8q+g, conflict-free)
//   Kt[c=64][68]   (row-major;      frag load bank = 4g+q, conflict-free)
//   Vt[c=64][72]   (row-major;      frag load bank = 8q+g, conflict-free)
//   Ps[r=128][68]  (A layout;       frag load bank = 4g+q, conflict-free)
// ---------------------------------------------------------------------------
#define QTS 136
#define KTS 68
#define VTS 72
#define PTS 68
#define ATT_SMEM ((64*QTS + 64*KTS + 64*VTS + 128*PTS + 64) * 4)

__global__ void __launch_bounds__(128)
attn_tf32(const int* __restrict__ mask)
{
    extern __shared__ unsigned sm[];
    unsigned* Qt = sm;                       // [64][136]
    unsigned* Kt = Qt + 64 * QTS;            // [64][68]
    unsigned* Vt = Kt + 64 * KTS;            // [64][72]
    unsigned* Ps = Vt + 64 * VTS;            // [128][68]
    float* maskF = (float*)(Ps + 128 * PTS); // [64]

    const int tid  = threadIdx.x;
    const int warp = tid >> 5;    // 0..3
    const int lane = tid & 31;
    const int g    = lane >> 2;   // 0..7
    const int q    = lane & 3;    // 0..3
    const int rb   = warp * 32;   // warp row base

    const int bh = blockIdx.y;
    const int b  = bh >> 4;
    const int h  = bh & 15;
    const int q0 = blockIdx.x * 128;

    // Load Q (pre-scaled by 0.125) transposed to [d][r]
    const float* qptr = g_q + ((size_t)bh * SS + q0) * DK;
    for (int e = tid; e < 128 * 16; e += 128) {
        int r  = e >> 4;
        int d4 = (e & 15) << 2;
        float4 v = *(const float4*)(qptr + (size_t)r * DK + d4);
        Qt[(d4 + 0) * QTS + r] = f2tf(v.x * 0.125f);
        Qt[(d4 + 1) * QTS + r] = f2tf(v.y * 0.125f);
        Qt[(d4 + 2) * QTS + r] = f2tf(v.z * 0.125f);
        Qt[(d4 + 3) * QTS + r] = f2tf(v.w * 0.125f);
    }

    float o[2][8][4];
    #pragma unroll
    for (int f = 0; f < 2; f++)
        #pragma unroll
        for (int nt = 0; nt < 8; nt++)
            #pragma unroll
            for (int i = 0; i < 4; i++) o[f][nt][i] = 0.0f;
    // per-thread rows: idx = f*2+half -> row rb + f*16 + g + half*8
    float mrow[4] = {-1e30f, -1e30f, -1e30f, -1e30f};
    float lrow[4] = {0.0f, 0.0f, 0.0f, 0.0f};

    for (int kt = 0; kt < SS / 64; kt++) {
        __syncthreads();   // prev iter done reading Kt/Vt/Ps

        // Stage K [c][k] and V [c][d], converted to tf32, STS.128
        const float* kp = g_k + ((size_t)bh * SS + kt * 64) * DK;
        const float* vp = g_v + ((size_t)bh * SS + kt * 64) * DK;
        for (int e = tid; e < 64 * 16; e += 128) {
            int c  = e >> 4;
            int d4 = (e & 15) << 2;
            float4 kv = *(const float4*)(kp + (size_t)c * DK + d4);
            uint4 ku = make_uint4(f2tf(kv.x), f2tf(kv.y), f2tf(kv.z), f2tf(kv.w));
            *(uint4*)&Kt[c * KTS + d4] = ku;
            float4 vv = *(const float4*)(vp + (size_t)c * DK + d4);
            uint4 vu = make_uint4(f2tf(vv.x), f2tf(vv.y), f2tf(vv.z), f2tf(vv.w));
            *(uint4*)&Vt[c * VTS + d4] = vu;
        }
        if (tid < 64)
            maskF[tid] = (mask[b * SS + kt * 64 + tid] == 0) ? 0.0f : 1.0f;
        __syncthreads();

        // ---- S = Q K^T : 2 m-frags x 8 n-frags ----
        float s[2][8][4];
        #pragma unroll
        for (int f = 0; f < 2; f++)
            #pragma unroll
            for (int nt = 0; nt < 8; nt++)
                #pragma unroll
                for (int i = 0; i < 4; i++) s[f][nt][i] = 0.0f;

        #pragma unroll
        for (int k8 = 0; k8 < 64; k8 += 8) {
            unsigned a[2][4];
            #pragma unroll
            for (int f = 0; f < 2; f++) {
                int r = rb + f * 16 + g;
                a[f][0] = Qt[(k8 + q) * QTS + r];
                a[f][1] = Qt[(k8 + q) * QTS + r + 8];
                a[f][2] = Qt[(k8 + 4 + q) * QTS + r];
                a[f][3] = Qt[(k8 + 4 + q) * QTS + r + 8];
            }
            #pragma unroll
            for (int nt = 0; nt < 8; nt++) {
                int c = nt * 8 + g;
                unsigned b0 = Kt[c * KTS + k8 + q];
                unsigned b1 = Kt[c * KTS + k8 + 4 + q];
                mma_tf32(s[0][nt][0], s[0][nt][1], s[0][nt][2], s[0][nt][3],
                         a[0][0], a[0][1], a[0][2], a[0][3], b0, b1);
                mma_tf32(s[1][nt][0], s[1][nt][1], s[1][nt][2], s[1][nt][3],
                         a[1][0], a[1][1], a[1][2], a[1][3], b0, b1);
            }
        }

        // ---- mask ----
        #pragma unroll
        for (int nt = 0; nt < 8; nt++) {
            float mk0 = maskF[nt * 8 + 2 * q];
            float mk1 = maskF[nt * 8 + 2 * q + 1];
            #pragma unroll
            for (int f = 0; f < 2; f++) {
                s[f][nt][0] = (mk0 == 0.0f) ? -10000.0f : s[f][nt][0];
                s[f][nt][2] = (mk0 == 0.0f) ? -10000.0f : s[f][nt][2];
                s[f][nt][1] = (mk1 == 0.0f) ? -10000.0f : s[f][nt][1];
                s[f][nt][3] = (mk1 == 0.0f) ? -10000.0f : s[f][nt][3];
            }
        }

        // ---- online softmax: 4 rows/thread (f x half), quad reduction ----
        #pragma unroll
        for (int f = 0; f < 2; f++) {
            #pragma unroll
            for (int half = 0; half < 2; half++) {
                int ri = f * 2 + half;
                float mx = -1e30f;
                #pragma unroll
                for (int nt = 0; nt < 8; nt++) {
                    mx = fmaxf(mx, s[f][nt][half * 2 + 0]);
                    mx = fmaxf(mx, s[f][nt][half * 2 + 1]);
                }
                mx = fmaxf(mx, __shfl_xor_sync(0xffffffffu, mx, 1));
                mx = fmaxf(mx, __shfl_xor_sync(0xffffffffu, mx, 2));
                float mnew  = fmaxf(mrow[ri], mx);
                float alpha = __expf(mrow[ri] - mnew);
                float rs = 0.0f;
                #pragma unroll
                for (int nt = 0; nt < 8; nt++) {
                    float p0 = __expf(s[f][nt][half * 2 + 0] - mnew);
                    float p1 = __expf(s[f][nt][half * 2 + 1] - mnew);
                    s[f][nt][half * 2 + 0] = p0;
                    s[f][nt][half * 2 + 1] = p1;
                    rs += p0 + p1;
                }
                rs += __shfl_xor_sync(0xffffffffu, rs, 1);
                rs += __shfl_xor_sync(0xffffffffu, rs, 2);
                lrow[ri] = lrow[ri] * alpha + rs;
                mrow[ri] = mnew;
                #pragma unroll
                for (int nt = 0; nt < 8; nt++) {
                    o[f][nt][half * 2 + 0] *= alpha;
                    o[f][nt][half * 2 + 1] *= alpha;
                }
            }
        }

        // ---- stage P in A layout [r][c] ----
        #pragma unroll
        for (int f = 0; f < 2; f++) {
            int r = rb + f * 16 + g;
            #pragma unroll
            for (int nt = 0; nt < 8; nt++) {
                Ps[r * PTS + nt * 8 + 2 * q]           = f2tf(s[f][nt][0]);
                Ps[r * PTS + nt * 8 + 2 * q + 1]       = f2tf(s[f][nt][1]);
                Ps[(r + 8) * PTS + nt * 8 + 2 * q]     = f2tf(s[f][nt][2]);
                Ps[(r + 8) * PTS + nt * 8 + 2 * q + 1] = f2tf(s[f][nt][3]);
            }
        }
        __syncthreads();

        // ---- O += P V ----
        #pragma unroll
        for (int c8 = 0; c8 < 64; c8 += 8) {
            unsigned a[2][4];
            #pragma unroll
            for (int f = 0; f < 2; f++) {
                int r = rb + f * 16 + g;
                a[f][0] = Ps[r * PTS + c8 + q];
                a[f][1] = Ps[(r + 8) * PTS + c8 + q];
                a[f][2] = Ps[r * PTS + c8 + 4 + q];
                a[f][3] = Ps[(r + 8) * PTS + c8 + 4 + q];
            }
            #pragma unroll
            for (int nt = 0; nt < 8; nt++) {
                int d = nt * 8 + g;
                unsigned b0 = Vt[(c8 + q) * VTS + d];
                unsigned b1 = Vt[(c8 + 4 + q) * VTS + d];
                mma_tf32(o[0][nt][0], o[0][nt][1], o[0][nt][2], o[0][nt][3],
                         a[0][0], a[0][1], a[0][2], a[0][3], b0, b1);
                mma_tf32(o[1][nt][0], o[1][nt][1], o[1][nt][2], o[1][nt][3],
                         a[1][0], a[1][1], a[1][2], a[1][3], b0, b1);
            }
        }
    }

    // Epilogue: normalize, write [b,s,hid]
    #pragma unroll
    for (int f = 0; f < 2; f++) {
        float inv0 = 1.0f / lrow[f * 2 + 0];
        float inv1 = 1.0f / lrow[f * 2 + 1];
        #pragma unroll
        for (int nt = 0; nt < 8; nt++) {
            int d = nt * 8 + 2 * q;
            int rowA = q0 + rb + f * 16 + g;
            int rowB = rowA + 8;
            float2 v0 = make_float2(o[f][nt][0] * inv0, o[f][nt][1] * inv0);
            float2 v1 = make_float2(o[f][nt][2] * inv1, o[f][nt][3] * inv1);
            *(float2*)&g_x[((size_t)b * SS + rowA) * HID + h * DK + d] = v0;
            *(float2*)&g_x[((size_t)b * SS + rowB) * HID + h * DK + d] = v1;
        }
    }
}

// ---------------------------------------------------------------------------
extern "C" void kernel_launch(void* const* d_in, const int* in_sizes, int n_in,
                              void* d_out, int out_size)
{
    const float* query = (const float*)d_in[0];
    const float* key   = (const float*)d_in[1];
    const float* value = (const float*)d_in[2];
    const float* bias  = (const float*)d_in[3];
    const int*   mask  = (const int*)d_in[4];
    const float* wq = (const float*)d_in[5];
    const float* bq = (const float*)d_in[6];
    const float* wk = (const float*)d_in[7];
    const float* bk = (const float*)d_in[8];
    const float* wv = (const float*)d_in[9];
    const float* bv = (const float*)d_in[10];
    const float* wo = (const float*)d_in[11];
    const float* bo = (const float*)d_in[12];
    float* out = (float*)d_out;

    float *qp, *kp, *vp, *xp;
    cudaGetSymbolAddress((void**)&qp, g_q);
    cudaGetSymbolAddress((void**)&kp, g_k);
    cudaGetSymbolAddress((void**)&vp, g_v);
    cudaGetSymbolAddress((void**)&xp, g_x);

    cudaFuncSetAttribute(attn_tf32,
                         cudaFuncAttributeMaxDynamicSharedMemorySize, ATT_SMEM);

    dim3 gg(HID / 128, MM / 128);   // (8, 32)
    gemm_tf32<<<gg, 256>>>(query, wq, bq, nullptr, qp, 1);
    gemm_tf32<<<gg, 256>>>(key,   wk, bk, bias,    kp, 1);
    gemm_tf32<<<gg, 256>>>(value, wv, bv, bias,    vp, 1);
    attn_tf32<<<dim3(SS / 128, BB * NH), 128, ATT_SMEM>>>(mask);
    gemm_tf32<<<gg, 256>>>(xp, wo, bo, nullptr, out, 0);
}